// round 3
// baseline (speedup 1.0000x reference)
#include <cuda_runtime.h>
#include <cuda_fp16.h>
#include <cstdint>

constexpr int B_ROWS = 8192;
constexpr int DIM    = 1024;
constexpr int TILE_M = 128;
constexpr int TILE_N = 512;
constexpr int KT     = 64;                 // K elems per stage (128 B rows fp16)
constexpr int NCHUNKS = DIM / KT;          // 16

// idesc kind::f16: dtype F32(bit4), atype=btype=F16(0), N=256 -> (N/8)<<17, M=128 -> (M/16)<<24
constexpr uint32_t IDESC_F16 = (1u << 4) | ((256u / 8u) << 17) | ((128u / 16u) << 24);

constexpr uint32_t A_TILE_BYTES = TILE_M * 128;                 // 16 KB
constexpr uint32_t B_TILE_BYTES = TILE_N * 128;                 // 64 KB
constexpr uint32_t STAGE_BYTES  = A_TILE_BYTES + B_TILE_BYTES;  // 80 KB (tcgen05 path)
constexpr uint32_t HDR_BYTES    = 1024;
constexpr uint32_t SMEM_DYN     = 1024 + HDR_BYTES + 2 * STAGE_BYTES;

// Fallback (HMMA) path: B subtile = 128 rows
constexpr uint32_t FB_B_BYTES   = 128 * 128;                    // 16 KB
constexpr uint32_t FB_STAGE     = A_TILE_BYTES + FB_B_BYTES;    // 32 KB

__device__ __half g_P16[(size_t)B_ROWS * DIM];
__device__ __half g_C16[(size_t)4 * B_ROWS * DIM];
__device__ __half g_W16[(size_t)3 * DIM * DIM];   // [0]=GWP^T [1]=GWC^T [2]=OW^T (K contiguous)
__device__ float  g_WP [(size_t)B_ROWS * DIM];    // P@GWP + GateBias
__device__ float  g_WPO[(size_t)B_ROWS * DIM];    // P@OW  + OutBias

// Does THIS device-compilation pass support tcgen05?
#if defined(__CUDA_ARCH__) && (defined(__CUDA_ARCH_FEAT_SM103_ALL) || defined(__CUDA_ARCH_FEAT_SM100_ALL) || defined(__CUDA_ARCH_FAMILY_SPECIFIC__))
#define USE_TC 1
#else
#define USE_TC 0
#endif

// ---------------- common PTX helpers (base PTX, legal on sm_103) ----------------
__device__ __forceinline__ uint32_t smem_u32(const void* p) {
    uint32_t a;
    asm("{ .reg .u64 t; cvta.to.shared.u64 t, %1; cvt.u32.u64 %0, t; }" : "=r"(a) : "l"(p));
    return a;
}
__device__ __forceinline__ uint32_t elect_one_pred() {
    uint32_t pred;
    asm volatile("{\n\t.reg .pred p;\n\telect.sync _|p, 0xFFFFFFFF;\n\tselp.b32 %0, 1, 0, p;\n\t}"
                 : "=r"(pred));
    return pred;
}
__device__ __forceinline__ uint32_t swz(uint32_t off) { return off ^ ((off >> 3) & 0x70); }

static constexpr uint64_t SMEM_DESC_BASE_SW128 =
    (uint64_t(2) << 61) | (uint64_t(1) << 46) | (uint64_t(64) << 32) | (uint64_t(1) << 16);
#define MAKE_SMEM_DESC(base_addr) \
    (SMEM_DESC_BASE_SW128 | ((uint64_t)((base_addr) >> 4) & 0x3FFF))

#define CP_ASYNC16(dst, src) \
    asm volatile("cp.async.cg.shared.global [%0], [%1], 16;" :: "r"(dst), "l"(src))

#define MBARRIER_INIT(addr, count) \
    asm volatile("mbarrier.init.shared.b64 [%0], %1;" :: "r"((uint32_t)(addr)), "r"((uint32_t)(count)) : "memory")

#define MBARRIER_WAIT_PARITY(mbar_smem_addr, phase_parity) do { \
    uint32_t _mbar = (uint32_t)(mbar_smem_addr); \
    uint32_t _parity = (uint32_t)(phase_parity); \
    uint32_t _done; \
    asm volatile( \
        "{\n\t.reg .pred p;\n\t" \
        "mbarrier.try_wait.parity.acquire.cta.shared::cta.b64 p, [%1], %2;\n\t" \
        "selp.b32 %0, 1, 0, p;\n\t}" \
        : "=r"(_done) : "r"(_mbar), "r"(_parity) : "memory"); \
    if (!_done) { \
        asm volatile( \
            "{\n\t.reg .pred P1;\n\t" \
            "WAIT_LOOP_%=:\n\t" \
            "mbarrier.try_wait.parity.acquire.cta.shared::cta.b64 P1, [%0], %1, 0x989680;\n\t" \
            "@P1 bra.uni WAIT_DONE_%=;\n\t" \
            "bra.uni WAIT_LOOP_%=;\n\t" \
            "WAIT_DONE_%=:\n\t}" \
            :: "r"(_mbar), "r"(_parity) : "memory"); \
    } \
} while (0)

// ---------------- tcgen05 macros (only expanded under USE_TC) ----------------
#define TCGEN05_ALLOC(smem_result_addr, nCols) \
    asm volatile("tcgen05.alloc.cta_group::1.sync.aligned.shared::cta.b32 [%0], %1;" \
                 :: "r"((uint32_t)(smem_result_addr)), "r"((uint32_t)(nCols)) : "memory")
#define TCGEN05_DEALLOC(tmem_addr, nCols) \
    asm volatile("tcgen05.dealloc.cta_group::1.sync.aligned.b32 %0, %1;" :: "r"(tmem_addr), "r"((uint32_t)(nCols)))
#define TCGEN05_COMMIT(mbar_smem_addr) \
    asm volatile("tcgen05.commit.cta_group::1.mbarrier::arrive::one.shared::cluster.b64 [%0];" \
                 :: "r"((uint32_t)(mbar_smem_addr)) : "memory")
#define TCGEN05_WAIT_LD()      asm volatile("tcgen05.wait::ld.sync.aligned;" ::: "memory")
#define TCGEN05_FENCE_BEFORE() asm volatile("tcgen05.fence::before_thread_sync;" ::: "memory")
#define TCGEN05_FENCE_AFTER()  asm volatile("tcgen05.fence::after_thread_sync;" ::: "memory")

#define MMA_F16_SS(d_tmem, a_desc, b_desc, idesc, enable_d) do { \
    uint32_t _en = (enable_d); \
    asm volatile( \
        "{\n\t.reg .pred p;\n\t" \
        "setp.ne.u32 p, %4, 0;\n\t" \
        "tcgen05.mma.cta_group::1.kind::f16 [%0], %1, %2, %3, {%5, %5, %5, %5}, p;\n\t}" \
        :: "r"(d_tmem), "l"(a_desc), "l"(b_desc), "r"(idesc), "r"(_en), "r"(0u) : "memory"); \
} while (0)

#define TCGEN05_LD_32X32B_X32(r, tmem_addr) \
    asm volatile( \
        "tcgen05.ld.sync.aligned.32x32b.x32.b32 " \
        "{%0, %1, %2, %3, %4, %5, %6, %7, " \
        " %8, %9, %10, %11, %12, %13, %14, %15, " \
        " %16, %17, %18, %19, %20, %21, %22, %23, " \
        " %24, %25, %26, %27, %28, %29, %30, %31}, [%32];" \
        : "=r"((r)[0]),  "=r"((r)[1]),  "=r"((r)[2]),  "=r"((r)[3]), \
          "=r"((r)[4]),  "=r"((r)[5]),  "=r"((r)[6]),  "=r"((r)[7]), \
          "=r"((r)[8]),  "=r"((r)[9]),  "=r"((r)[10]), "=r"((r)[11]), \
          "=r"((r)[12]), "=r"((r)[13]), "=r"((r)[14]), "=r"((r)[15]), \
          "=r"((r)[16]), "=r"((r)[17]), "=r"((r)[18]), "=r"((r)[19]), \
          "=r"((r)[20]), "=r"((r)[21]), "=r"((r)[22]), "=r"((r)[23]), \
          "=r"((r)[24]), "=r"((r)[25]), "=r"((r)[26]), "=r"((r)[27]), \
          "=r"((r)[28]), "=r"((r)[29]), "=r"((r)[30]), "=r"((r)[31]) \
        : "r"(tmem_addr))

// ---------------- fallback (HMMA) helpers ----------------
__device__ __forceinline__ void ldsm_x4(uint32_t addr, uint32_t& r0, uint32_t& r1,
                                        uint32_t& r2, uint32_t& r3) {
    asm volatile("ldmatrix.sync.aligned.m8n8.x4.shared.b16 {%0,%1,%2,%3}, [%4];"
                 : "=r"(r0), "=r"(r1), "=r"(r2), "=r"(r3) : "r"(addr));
}
__device__ __forceinline__ void mma16816(float* d, const uint32_t* a, const uint32_t* b) {
    asm volatile(
        "mma.sync.aligned.m16n8k16.row.col.f32.f16.f16.f32 "
        "{%0,%1,%2,%3},{%4,%5,%6,%7},{%8,%9},{%0,%1,%2,%3};"
        : "+f"(d[0]), "+f"(d[1]), "+f"(d[2]), "+f"(d[3])
        : "r"(a[0]), "r"(a[1]), "r"(a[2]), "r"(a[3]), "r"(b[0]), "r"(b[1]));
}

// Fill one K-chunk stage: A 128 rows + B NB rows, each row 128 B (KT=64 fp16), SW128 swizzled.
template <int NB>
__device__ __forceinline__ void fill_stage(const __half* __restrict__ gA,
                                           const __half* __restrict__ gB,
                                           int k0, uint32_t aB) {
    const int tid = threadIdx.x;
    uint32_t bB = aB + A_TILE_BYTES;
#pragma unroll
    for (int it = 0; it < 8; ++it) {
        int item = it * 128 + tid;
        int r = item >> 3, c = item & 7;
        CP_ASYNC16(aB + swz((uint32_t)(r * 128 + c * 16)), gA + (size_t)r * DIM + k0 + c * 8);
    }
#pragma unroll
    for (int it = 0; it < NB / 16; ++it) {
        int item = it * 128 + tid;
        int r = item >> 3, c = item & 7;
        CP_ASYNC16(bB + swz((uint32_t)(r * 128 + c * 16)), gB + (size_t)r * DIM + k0 + c * 8);
    }
}

// Fallback consume: one K-chunk (KT=64), warp computes 32(M) x 128(N) into d[2][16][4]
__device__ __forceinline__ void fb_consume(uint32_t aB, uint32_t bB, int w, int lane,
                                           float d[2][16][4]) {
    int g  = lane >> 3;   // ldmatrix sub-matrix id
    int lr = lane & 7;
#pragma unroll
    for (int c = 0; c < 4; ++c) {       // k16 steps within the 64-chunk
        uint32_t a[2][4];
#pragma unroll
        for (int t = 0; t < 2; ++t) {
            int row  = w * 32 + t * 16 + (g & 1) * 8 + lr;
            int unit = 2 * c + (g >> 1);
            ldsm_x4(aB + swz((uint32_t)(row * 128 + unit * 16)), a[t][0], a[t][1], a[t][2], a[t][3]);
        }
        uint32_t b[16][2];
#pragma unroll
        for (int j = 0; j < 8; ++j) {
            int row  = j * 16 + (g >> 1) * 8 + lr;
            int unit = 2 * c + (g & 1);
            ldsm_x4(bB + swz((uint32_t)(row * 128 + unit * 16)),
                    b[2 * j][0], b[2 * j][1], b[2 * j + 1][0], b[2 * j + 1][1]);
        }
#pragma unroll
        for (int t = 0; t < 2; ++t)
#pragma unroll
            for (int j = 0; j < 16; ++j) mma16816(d[t][j], a[t], b[j]);
    }
}

// ---------------- convert kernels ----------------
__global__ void convert_act_kernel(const float* __restrict__ P,
                                   const float* __restrict__ C1, const float* __restrict__ C2,
                                   const float* __restrict__ C3, const float* __restrict__ C4,
                                   float* __restrict__ out) {
    int y = blockIdx.y;
    const float* src = (y == 0) ? P : (y == 1) ? C1 : (y == 2) ? C2 : (y == 3) ? C3 : C4;
    __half* dst = (y == 0) ? g_P16 : (g_C16 + (size_t)(y - 1) * B_ROWS * DIM);
    size_t t = (size_t)blockIdx.x * 256 + threadIdx.x;
    size_t i = t * 4;
    float4 v = *(const float4*)(src + i);
    __half2 h0 = __floats2half2_rn(v.x, v.y);
    __half2 h1 = __floats2half2_rn(v.z, v.w);
    uint2 u;
    u.x = *reinterpret_cast<unsigned*>(&h0);
    u.y = *reinterpret_cast<unsigned*>(&h1);
    *reinterpret_cast<uint2*>(dst + i) = u;
    if (y == 0 && t < (size_t)(B_ROWS * 4 / 4)) {
        reinterpret_cast<float4*>(out)[t] = make_float4(0.f, 0.f, 0.f, 0.f);
    }
}

__global__ void convert_w_kernel(const float* __restrict__ GWP,
                                 const float* __restrict__ GWC,
                                 const float* __restrict__ OW) {
    __shared__ float t[32][33];
    const float* src = (blockIdx.z == 0) ? GWP : (blockIdx.z == 1) ? GWC : OW;
    __half* dst = g_W16 + (size_t)blockIdx.z * DIM * DIM;
    int tx = threadIdx.x, ty = threadIdx.y;
#pragma unroll
    for (int j = 0; j < 4; j++) {
        int k = blockIdx.y * 32 + ty + j * 8;
        int n = blockIdx.x * 32 + tx;
        t[ty + j * 8][tx] = src[(size_t)k * DIM + n];
    }
    __syncthreads();
#pragma unroll
    for (int j = 0; j < 4; j++) {
        int n = blockIdx.x * 32 + ty + j * 8;
        int k = blockIdx.y * 32 + tx;
        dst[(size_t)n * DIM + k] = __float2half_rn(t[tx][ty + j * 8]);
    }
}

#if USE_TC
// ---------------- tcgen05 mainloop ----------------
__device__ __forceinline__ void gemm_mainloop(const __half* __restrict__ gA,
                                              const __half* __restrict__ gB,
                                              uint32_t sb, uint32_t tmem) {
    const int tid = threadIdx.x;
    const uint32_t mbar0 = sb + 16;
    const uint32_t buf = sb + HDR_BYTES;

#pragma unroll 1
    for (int i = 0; i < NCHUNKS + 1; ++i) {
        if (i < NCHUNKS) {
            if (i >= 2) {
                int idx = (i - 2) >> 1;
                MBARRIER_WAIT_PARITY(mbar0 + (i & 1) * 8, idx & 1);
            }
            fill_stage<TILE_N>(gA, gB, i * KT, buf + (uint32_t)(i & 1) * STAGE_BYTES);
            asm volatile("cp.async.commit_group;" ::: "memory");
        }
        if (i >= 1) {
            if (i < NCHUNKS) { asm volatile("cp.async.wait_group 1;" ::: "memory"); }
            else             { asm volatile("cp.async.wait_group 0;" ::: "memory"); }
            __syncthreads();
            asm volatile("fence.proxy.async.shared::cta;" ::: "memory");
            if (tid < 32) {
                if (elect_one_pred()) {
                    int j = i - 1;
                    uint32_t aB = buf + (uint32_t)(j & 1) * STAGE_BYTES;
                    uint64_t ad = MAKE_SMEM_DESC(aB);
                    uint64_t bd = MAKE_SMEM_DESC(aB + A_TILE_BYTES);
#pragma unroll
                    for (int ks = 0; ks < 4; ++ks) {
                        uint32_t en = (j > 0 || ks > 0) ? 1u : 0u;
                        MMA_F16_SS(tmem,       ad + ks * 2, bd + ks * 2,        IDESC_F16, en);
                        MMA_F16_SS(tmem + 256, ad + ks * 2, bd + 2048 + ks * 2, IDESC_F16, en);
                    }
                    TCGEN05_COMMIT(mbar0 + (j & 1) * 8);
                }
            }
        }
    }
    MBARRIER_WAIT_PARITY(mbar0 + 8, 1);  // final commit (idx 7 on mbar1) -> parity 1
    TCGEN05_FENCE_AFTER();
}

__device__ __forceinline__ uint32_t gemm_prologue(uint32_t sb) {
    if ((threadIdx.x >> 5) == 0) TCGEN05_ALLOC(sb, 512);
    __syncthreads();
    uint32_t tmem;
    asm volatile("ld.shared.b32 %0, [%1];" : "=r"(tmem) : "r"(sb));
    if (threadIdx.x == 0) {
        MBARRIER_INIT(sb + 16, 1);
        MBARRIER_INIT(sb + 24, 1);
    }
    __syncthreads();
    return tmem;
}
#endif  // USE_TC

// ---------------- Stage A: WP = P@GWP + GateBias ; WPO = P@OW + OutBias ----------------
__global__ void __launch_bounds__(128, 1)
gemm_a_kernel(const float* __restrict__ GateBias, const float* __restrict__ OutBias) {
    extern __shared__ char smem_raw[];
    uint32_t sb = (smem_u32(smem_raw) + 1023u) & ~1023u;
    const int mb = blockIdx.x;
    const int ny = blockIdx.y;          // 0,1 -> WP halves; 2,3 -> WPO halves
    const int n0 = (ny & 1) * TILE_N;
    const __half* gA = g_P16 + (size_t)mb * TILE_M * DIM;
    const __half* gBb = g_W16 + (size_t)(ny < 2 ? 0 : 2) * DIM * DIM + (size_t)n0 * DIM;
    const float* bias = (ny < 2) ? GateBias : OutBias;
    float* dst = (ny < 2) ? g_WP : g_WPO;
    int wid = threadIdx.x >> 5, lane = threadIdx.x & 31;

#if USE_TC
    uint32_t tmem = gemm_prologue(sb);
    gemm_mainloop(gA, gBb, sb, tmem);
    int row = mb * TILE_M + wid * 32 + lane;
#pragma unroll 1
    for (int c0 = 0; c0 < TILE_N; c0 += 32) {
        uint32_t d[32];
        TCGEN05_LD_32X32B_X32(d, tmem + c0);
        TCGEN05_WAIT_LD();
#pragma unroll
        for (int jj = 0; jj < 8; jj++) {
            float4 b = *(const float4*)(bias + n0 + c0 + jj * 4);
            float4 o;
            o.x = __uint_as_float(d[jj * 4 + 0]) + b.x;
            o.y = __uint_as_float(d[jj * 4 + 1]) + b.y;
            o.z = __uint_as_float(d[jj * 4 + 2]) + b.z;
            o.w = __uint_as_float(d[jj * 4 + 3]) + b.w;
            *(float4*)(dst + (size_t)row * DIM + n0 + c0 + jj * 4) = o;
        }
    }
    TCGEN05_FENCE_BEFORE();
    __syncthreads();
    if ((threadIdx.x >> 5) == 0) TCGEN05_DEALLOC(tmem, 512);
#else
    const uint32_t buf = sb + HDR_BYTES;
#pragma unroll 1
    for (int ns = 0; ns < 4; ++ns) {
        const __half* gB = gBb + (size_t)ns * 128 * DIM;
        float d[2][16][4] = {};
        fill_stage<128>(gA, gB, 0, buf);
        asm volatile("cp.async.commit_group;" ::: "memory");
#pragma unroll 1
        for (int c2 = 0; c2 < 16; ++c2) {
            if (c2 < 15) {
                fill_stage<128>(gA, gB, (c2 + 1) * KT, buf + (uint32_t)((c2 + 1) & 1) * FB_STAGE);
                asm volatile("cp.async.commit_group;" ::: "memory");
                asm volatile("cp.async.wait_group 1;" ::: "memory");
            } else {
                asm volatile("cp.async.wait_group 0;" ::: "memory");
            }
            __syncthreads();
            uint32_t aB = buf + (uint32_t)(c2 & 1) * FB_STAGE;
            fb_consume(aB, aB + A_TILE_BYTES, wid, lane, d);
            __syncthreads();
        }
        int colb = n0 + ns * 128;
#pragma unroll
        for (int t = 0; t < 2; ++t)
#pragma unroll
            for (int j = 0; j < 16; ++j) {
                int row = mb * TILE_M + wid * 32 + t * 16 + (lane >> 2);
                int col = colb + j * 8 + (lane & 3) * 2;
                float2 bb = *(const float2*)(bias + col);
                float2 o0 = make_float2(d[t][j][0] + bb.x, d[t][j][1] + bb.y);
                float2 o1 = make_float2(d[t][j][2] + bb.x, d[t][j][3] + bb.y);
                *(float2*)(dst + (size_t)row * DIM + col) = o0;
                *(float2*)(dst + (size_t)(row + 8) * DIM + col) = o1;
            }
    }
#endif
}

// ---------------- Stage B: WC = C_k@GWC ; fused gate + score reduction ----------------
__global__ void __launch_bounds__(128, 1)
gemm_b_kernel(const float* __restrict__ C1, const float* __restrict__ C2,
              const float* __restrict__ C3, const float* __restrict__ C4,
              float* __restrict__ out) {
    extern __shared__ char smem_raw[];
    uint32_t sb = (smem_u32(smem_raw) + 1023u) & ~1023u;
    const int mb = blockIdx.x;
    const int nh = blockIdx.y;          // 0,1
    const int k  = blockIdx.z;          // branch 0..3
    const int n0 = nh * TILE_N;
    const __half* gA = g_C16 + (size_t)k * B_ROWS * DIM + (size_t)mb * TILE_M * DIM;
    const __half* gBb = g_W16 + (size_t)1 * DIM * DIM + (size_t)n0 * DIM;   // GWC^T
    const float* Ck = (k == 0) ? C1 : (k == 1) ? C2 : (k == 2) ? C3 : C4;
    int wid = threadIdx.x >> 5, lane = threadIdx.x & 31;

#if USE_TC
    uint32_t tmem = gemm_prologue(sb);
    gemm_mainloop(gA, gBb, sb, tmem);
    int row = mb * TILE_M + wid * 32 + lane;
    const float* wp_row = g_WP  + (size_t)row * DIM + n0;
    const float* wq_row = g_WPO + (size_t)row * DIM + n0;
    const float* c_row  = Ck + (size_t)row * DIM + n0;
    float score = 0.f;
#pragma unroll 1
    for (int c0 = 0; c0 < TILE_N; c0 += 32) {
        uint32_t d[32];
        TCGEN05_LD_32X32B_X32(d, tmem + c0);
        TCGEN05_WAIT_LD();
#pragma unroll
        for (int jj = 0; jj < 8; jj++) {
            float4 wp = *(const float4*)(wp_row + c0 + jj * 4);
            float4 wq = *(const float4*)(wq_row + c0 + jj * 4);
            float4 cv = *(const float4*)(c_row  + c0 + jj * 4);
            float z, g;
            z = __uint_as_float(d[jj * 4 + 0]) + wp.x;
            g = __fdividef(1.f, 1.f + __expf(-z)); score += cv.x * g * wq.x;
            z = __uint_as_float(d[jj * 4 + 1]) + wp.y;
            g = __fdividef(1.f, 1.f + __expf(-z)); score += cv.y * g * wq.y;
            z = __uint_as_float(d[jj * 4 + 2]) + wp.z;
            g = __fdividef(1.f, 1.f + __expf(-z)); score += cv.z * g * wq.z;
            z = __uint_as_float(d[jj * 4 + 3]) + wp.w;
            g = __fdividef(1.f, 1.f + __expf(-z)); score += cv.w * g * wq.w;
        }
    }
    atomicAdd(out + (size_t)row * 4 + k, score);
    TCGEN05_FENCE_BEFORE();
    __syncthreads();
    if ((threadIdx.x >> 5) == 0) TCGEN05_DEALLOC(tmem, 512);
#else
    const uint32_t buf = sb + HDR_BYTES;
    float s[4] = {0.f, 0.f, 0.f, 0.f};   // rows: t*16 + lane/4 + h*8
#pragma unroll 1
    for (int ns = 0; ns < 4; ++ns) {
        const __half* gB = gBb + (size_t)ns * 128 * DIM;
        float d[2][16][4] = {};
        fill_stage<128>(gA, gB, 0, buf);
        asm volatile("cp.async.commit_group;" ::: "memory");
#pragma unroll 1
        for (int c2 = 0; c2 < 16; ++c2) {
            if (c2 < 15) {
                fill_stage<128>(gA, gB, (c2 + 1) * KT, buf + (uint32_t)((c2 + 1) & 1) * FB_STAGE);
                asm volatile("cp.async.commit_group;" ::: "memory");
                asm volatile("cp.async.wait_group 1;" ::: "memory");
            } else {
                asm volatile("cp.async.wait_group 0;" ::: "memory");
            }
            __syncthreads();
            uint32_t aB = buf + (uint32_t)(c2 & 1) * FB_STAGE;
            fb_consume(aB, aB + A_TILE_BYTES, wid, lane, d);
            __syncthreads();
        }
        int colb = n0 + ns * 128;
#pragma unroll
        for (int t = 0; t < 2; ++t)
#pragma unroll
            for (int j = 0; j < 16; ++j) {
                int col = colb + j * 8 + (lane & 3) * 2;
#pragma unroll
                for (int h = 0; h < 2; ++h) {
                    int row = mb * TILE_M + wid * 32 + t * 16 + (lane >> 2) + h * 8;
                    float2 wp = *(const float2*)(g_WP  + (size_t)row * DIM + col);
                    float2 wq = *(const float2*)(g_WPO + (size_t)row * DIM + col);
                    float2 cv = *(const float2*)(Ck    + (size_t)row * DIM + col);
                    float z, g;
                    z = d[t][j][h * 2 + 0] + wp.x;
                    g = __fdividef(1.f, 1.f + __expf(-z)); s[t * 2 + h] += cv.x * g * wq.x;
                    z = d[t][j][h * 2 + 1] + wp.y;
                    g = __fdividef(1.f, 1.f + __expf(-z)); s[t * 2 + h] += cv.y * g * wq.y;
                }
            }
    }
    // reduce across the 4 lanes sharing each row
#pragma unroll
    for (int i = 0; i < 4; ++i) {
        s[i] += __shfl_xor_sync(0xffffffff, s[i], 1);
        s[i] += __shfl_xor_sync(0xffffffff, s[i], 2);
    }
    if ((lane & 3) == 0) {
#pragma unroll
        for (int t = 0; t < 2; ++t)
#pragma unroll
            for (int h = 0; h < 2; ++h) {
                int row = mb * TILE_M + wid * 32 + t * 16 + (lane >> 2) + h * 8;
                atomicAdd(out + (size_t)row * 4 + k, s[t * 2 + h]);
            }
    }
#endif
}

// ---------------- launch ----------------
extern "C" void kernel_launch(void* const* d_in, const int* in_sizes, int n_in,
                              void* d_out, int out_size) {
    const float* P   = (const float*)d_in[0];
    const float* C1  = (const float*)d_in[1];
    const float* C2  = (const float*)d_in[2];
    const float* C3  = (const float*)d_in[3];
    const float* C4  = (const float*)d_in[4];
    const float* GWP = (const float*)d_in[5];
    const float* GWC = (const float*)d_in[6];
    const float* GB  = (const float*)d_in[7];
    const float* OW  = (const float*)d_in[8];
    const float* OB  = (const float*)d_in[9];
    float* out = (float*)d_out;

    cudaFuncSetAttribute(gemm_a_kernel, cudaFuncAttributeMaxDynamicSharedMemorySize, SMEM_DYN);
    cudaFuncSetAttribute(gemm_b_kernel, cudaFuncAttributeMaxDynamicSharedMemorySize, SMEM_DYN);

    convert_act_kernel<<<dim3(B_ROWS * DIM / 4 / 256, 5), 256>>>(P, C1, C2, C3, C4, out);
    convert_w_kernel<<<dim3(DIM / 32, DIM / 32, 3), dim3(32, 8)>>>(GWP, GWC, OW);
    gemm_a_kernel<<<dim3(B_ROWS / TILE_M, 4), 128, SMEM_DYN>>>(GB, OB);
    gemm_b_kernel<<<dim3(B_ROWS / TILE_M, 2, 4), 128, SMEM_DYN>>>(C1, C2, C3, C4, out);
}